// round 14
// baseline (speedup 1.0000x reference)
#include <cuda_runtime.h>
#include <cuda_fp16.h>
#include <math.h>

#define TAU 0.07f
#define EPSN 1e-12f

constexpr int B_   = 4;
constexpr int C_   = 256;
constexpr int K_   = 19;
constexpr int HW   = 65536;          // 256*256
constexpr int P    = B_ * HW;        // 262144
constexpr int NBLK = 296;            // persistent CTAs (2/SM) == resident set
constexpr int KC   = K_ * C_;        // 4864
// phase A
constexpr int TQ   = 32;             // pixels per tile
constexpr int NTA  = P / TQ;         // 8192 tiles
constexpr int TSA  = 40;             // tile pixel-stride (40%32==8 -> LDS.64 conflict-free)
// phase C
constexpr int PS    = 260;           // slab pixel-stride (260%32==4 -> conflict-free)
constexpr int CTILE = 256;           // pixels per tile
constexpr int NCT   = P / CTILE;     // 1024
constexpr int SLABC = 16;            // channels per chunk
constexpr int WS    = 40;            // class stride (half2 units)

// ---- scratch (static __device__, no allocation) ----
__device__ float    g_part[(size_t)NBLK * KC];
__device__ float2   g_npr[P];
__device__ float    g_k0n[KC];
__device__ float    g_normk[K_];
__device__ int      g_nposblk[NBLK];
__device__ float    g_lsepart[NBLK];
__device__ unsigned g_c0, g_c1, g_c2;    // grid barrier counters (reset each run)

// ---- PTX helpers ----
__device__ __forceinline__ unsigned smem_u32(const void* p) {
    return (unsigned)__cvta_generic_to_shared(p);
}
__device__ __forceinline__ void cp16(unsigned dst, const void* src) {
    asm volatile("cp.async.cg.shared.global [%0], [%1], 16;\n" :: "r"(dst), "l"(src));
}
__device__ __forceinline__ void cp_commit() { asm volatile("cp.async.commit_group;\n" ::: "memory"); }
template<int N> __device__ __forceinline__ void cp_wait() {
    asm volatile("cp.async.wait_group %0;\n" :: "n"(N) : "memory");
}
__device__ __forceinline__ unsigned pack_h2(float lo, float hi) {
    unsigned r;
    asm("cvt.rn.f16x2.f32 %0, %1, %2;" : "=r"(r) : "f"(hi), "f"(lo));
    return r;
}
__device__ __forceinline__ void mma_f16(float* d, const unsigned* a, const unsigned* b) {
    asm volatile(
        "mma.sync.aligned.m16n8k16.row.col.f32.f16.f16.f32 "
        "{%0,%1,%2,%3}, {%4,%5,%6,%7}, {%8,%9}, {%0,%1,%2,%3};\n"
        : "+f"(d[0]), "+f"(d[1]), "+f"(d[2]), "+f"(d[3])
        : "r"(a[0]), "r"(a[1]), "r"(a[2]), "r"(a[3]), "r"(b[0]), "r"(b[1]));
}
// grid-wide barrier: all NBLK CTAs resident by construction
__device__ __forceinline__ void grid_bar(unsigned* ctr) {
    __syncthreads();
    if (threadIdx.x == 0) {
        __threadfence();
        atomicAdd(ctr, 1u);
        while (*(volatile unsigned*)ctr < (unsigned)NBLK) __nanosleep(32);
        __threadfence();
    }
    __syncthreads();
}

// ============================================================
// Single fused kernel: A (k0 partials) -> B (prototypes) ->
// C (logits+lse) -> D (final scalar), grid barriers between.
// ============================================================
extern "C" __global__ void __launch_bounds__(256, 2)
kF(const float* __restrict__ feat, const float* __restrict__ gt,
   float* __restrict__ out)
{
    extern __shared__ float sm[];
    __shared__ float sred[256];
    __shared__ int   sredi[256];
    __shared__ int   sflag;

    const int tid  = threadIdx.x;
    const int blk  = blockIdx.x;
    const int lane = tid & 31;
    const int wrp  = tid >> 5;
    const int g    = lane >> 2;
    const int tg   = lane & 3;

    // ======================= PHASE A =======================
    {
        float*    fbuf = sm;                               // 2 x [256][40]
        unsigned* wk   = (unsigned*)(sm + 2 * C_ * TSA);   // 2 x [16 pairs][40]
        float*    sgt  = (float*)(wk + 2 * 16 * WS);       // 2 x [19][32]
        float*    ssq  = sgt + 2 * K_ * TQ;                // [256]

        const int qi = tid & 7;        // staging float4 slot
        const int cr = tid >> 3;       // staging channel base (0..31)

        for (int i = tid; i < 2 * 16 * WS; i += 256) wk[i] = 0u;
        __syncthreads();

        float acc[2][3][4];
#pragma unroll
        for (int mt = 0; mt < 2; mt++)
#pragma unroll
            for (int nt = 0; nt < 3; nt++)
#pragma unroll
                for (int r = 0; r < 4; r++) acc[mt][nt][r] = 0.f;
        int np_acc = 0;

        auto issue = [&](int jj) {
            const int t = blk + jj * NBLK;
            if (t < NTA) {
                float* buf = fbuf + (jj & 1) * (C_ * TSA);
                const int p0  = t * TQ;
                const int b   = p0 >> 16;
                const int hw0 = p0 & 65535;
                const float* fb = feat + (size_t)b * C_ * HW + hw0;
#pragma unroll
                for (int i = 0; i < 8; i++) {
                    const int c = cr + 32 * i;
                    cp16(smem_u32(buf + c * TSA + qi * 4), fb + (size_t)c * HW + qi * 4);
                }
                if (tid < (K_ * TQ) / 4) {
                    const int k  = tid >> 3;
                    const int qq = (tid & 7) * 4;
                    cp16(smem_u32(sgt + (jj & 1) * (K_ * TQ) + k * TQ + qq),
                         gt + (size_t)b * K_ * HW + hw0 + (size_t)k * HW + qq);
                }
            }
            cp_commit();
        };

        auto dossq = [&](int jj) {
            const float* col = fbuf + (jj & 1) * (C_ * TSA) + (wrp * 32) * TSA + lane;
            float a0 = 0.f, a1 = 0.f, a2 = 0.f, a3 = 0.f;
#pragma unroll
            for (int cc = 0; cc < 32; cc += 4) {
                const float v0 = col[(cc + 0) * TSA];
                const float v1 = col[(cc + 1) * TSA];
                const float v2 = col[(cc + 2) * TSA];
                const float v3 = col[(cc + 3) * TSA];
                a0 = fmaf(v0, v0, a0); a1 = fmaf(v1, v1, a1);
                a2 = fmaf(v2, v2, a2); a3 = fmaf(v3, v3, a3);
            }
            ssq[wrp * 32 + lane] = (a0 + a1) + (a2 + a3);
        };

        auto domask = [&](int jj, int t) {
            if (tid < TQ) {
                const int q = tid;
                float s = 0.f;
#pragma unroll
                for (int w = 0; w < 8; w++) s += ssq[w * 32 + q];
                const float rn = 1.0f / fmaxf(sqrtf(s), EPSN);
                const __half rnh  = __float2half_rn(rn);
                const __half zero = __float2half_rn(0.f);
                __half* wh = (__half*)(wk + (jj & 1) * (16 * WS));
                const float* gtt = sgt + (jj & 1) * (K_ * TQ);
                const int base = ((q >> 1) * WS) * 2 + (q & 1);
                int np = 0;
#pragma unroll
                for (int k = 0; k < K_; k++) {
                    const bool pos = (gtt[k * TQ + q] == 1.0f);
                    wh[base + 2 * k] = pos ? rnh : zero;
                    np += pos ? 1 : 0;
                }
                g_npr[t * TQ + q] = make_float2((float)np, rn);
                np_acc += np;
            }
        };

        auto compute = [&](int jj) {
            const float*    cur = fbuf + (jj & 1) * (C_ * TSA);
            const unsigned* wks = wk + (jj & 1) * (16 * WS);
            const int R = wrp * 32;
#pragma unroll
            for (int q16 = 0; q16 < 2; q16++) {
                const int p0 = 16 * q16;
                unsigned a[2][4];
#pragma unroll
                for (int mt = 0; mt < 2; mt++) {
                    const float* base = cur + (R + 16 * mt + g) * TSA + p0 + 2 * tg;
                    const float2 u0 = *(const float2*)(base);
                    const float2 u1 = *(const float2*)(base + 8 * TSA);
                    const float2 u2 = *(const float2*)(base + 8);
                    const float2 u3 = *(const float2*)(base + 8 * TSA + 8);
                    a[mt][0] = pack_h2(u0.x, u0.y);
                    a[mt][1] = pack_h2(u1.x, u1.y);
                    a[mt][2] = pack_h2(u2.x, u2.y);
                    a[mt][3] = pack_h2(u3.x, u3.y);
                }
#pragma unroll
                for (int nt = 0; nt < 3; nt++) {
                    unsigned b[2];
                    b[0] = wks[(p0 / 2 + tg) * WS + 8 * nt + g];
                    b[1] = wks[(p0 / 2 + tg + 4) * WS + 8 * nt + g];
                    mma_f16(acc[0][nt], a[0], b);
                    mma_f16(acc[1][nt], a[1], b);
                }
            }
        };

        issue(0); issue(1);
        int j = 0;
        while (blk + j * NBLK < NTA) {
            cp_wait<1>();
            __syncthreads();
            dossq(j);
            __syncthreads();
            domask(j, blk + j * NBLK);
            __syncthreads();
            compute(j);
            __syncthreads();
            issue(j + 2);
            j++;
        }
        cp_wait<0>();   // drain stale (possibly empty) groups before phase C reuses smem

        const int R = wrp * 32;
#pragma unroll
        for (int mt = 0; mt < 2; mt++)
#pragma unroll
            for (int nt = 0; nt < 3; nt++)
#pragma unroll
                for (int r = 0; r < 4; r++) {
                    const int row = R + 16 * mt + g + 8 * (r >> 1);
                    const int col = 8 * nt + 2 * tg + (r & 1);
                    if (col < K_)
                        g_part[(size_t)blk * KC + col * C_ + row] = acc[mt][nt][r];
                }

        __syncthreads();
        int* si = (int*)ssq;
        if (tid < TQ) si[tid] = np_acc;
        __syncthreads();
        if (tid == 0) {
            int s = 0;
            for (int i = 0; i < TQ; i++) s += si[i];
            g_nposblk[blk] = s;
        }
        __syncthreads();
    }

    // ================ PHASE C layout + prefetch ================
    float*    ring = sm;                                 // 4 x [16][260]
    unsigned* sbh  = (unsigned*)(sm + 4 * SLABC * PS);   // [128 ch-pairs][40]

    const int qi = tid & 63;
    const int cr = tid >> 6;

    auto issueC = [&](int m) {
        const int tile = blk + (m >> 4) * NBLK;
        if (tile < NCT) {
            const int s  = m & 15;
            const int c0 = s * SLABC;
            float* buf = ring + (m & 3) * (SLABC * PS);
            const int p0  = tile * CTILE;
            const int b   = p0 >> 16;
            const int hw0 = p0 & 65535;
            const float* fb = feat + (size_t)b * C_ * HW + hw0 + qi * 4;
#pragma unroll
            for (int i = 0; i < 4; i++) {
                const int cl = cr + 4 * i;
                cp16(smem_u32(buf + cl * PS + qi * 4), fb + (size_t)(c0 + cl) * HW);
            }
        }
        cp_commit();
    };

    // feat prefetch is independent of k0n: start streaming now
    issueC(0); issueC(1); issueC(2);

    // ======================= PHASE B =======================
    grid_bar(&g_c0);     // all g_part/g_npr visible

    if (blk < K_) {      // 19 CTAs reduce prototypes; rest keep prefetch warm
        const int k = blk;
        const int c = tid;
        float v0 = 0.f, v1 = 0.f, v2 = 0.f, v3 = 0.f,
              v4 = 0.f, v5 = 0.f, v6 = 0.f, v7 = 0.f;
        const float* gp = g_part + (size_t)k * C_ + c;
#pragma unroll 1
        for (int b = 0; b < NBLK; b += 8) {     // 296 = 37*8
            v0 += gp[(size_t)(b + 0) * KC];
            v1 += gp[(size_t)(b + 1) * KC];
            v2 += gp[(size_t)(b + 2) * KC];
            v3 += gp[(size_t)(b + 3) * KC];
            v4 += gp[(size_t)(b + 4) * KC];
            v5 += gp[(size_t)(b + 5) * KC];
            v6 += gp[(size_t)(b + 6) * KC];
            v7 += gp[(size_t)(b + 7) * KC];
        }
        const float v = ((v0 + v1) + (v2 + v3)) + ((v4 + v5) + (v6 + v7));
        sred[c] = v * v;
        __syncthreads();
        for (int st = 128; st > 0; st >>= 1) {
            if (tid < st) sred[tid] += sred[tid + st];
            __syncthreads();
        }
        const float ssq = sred[0];
        const float inv = 1.0f / fmaxf(sqrtf(ssq), EPSN);
        g_k0n[k * C_ + c] = v * inv;
        if (c == 0) g_normk[k] = ssq * inv;   // = k0n . k0
        __syncthreads();
    }

    grid_bar(&g_c1);     // k0n ready everywhere
    if (blk == 0 && tid == 0) g_c0 = 0;   // safe: all CTAs past c0 spin

    // ======================= PHASE C =======================
    for (int i = tid; i < 128 * WS; i += 256) sbh[i] = 0u;
    __syncthreads();
    for (int idx = tid; idx < 128 * K_; idx += 256) {
        const int cp = idx / K_;
        const int k  = idx - cp * K_;
        sbh[cp * WS + k] = pack_h2(g_k0n[k * C_ + 2 * cp],
                                   g_k0n[k * C_ + 2 * cp + 1]);
    }
    __syncthreads();

    float acc[2][3][4];
#pragma unroll
    for (int mt = 0; mt < 2; mt++)
#pragma unroll
        for (int nt = 0; nt < 3; nt++)
#pragma unroll
            for (int r = 0; r < 4; r++) acc[mt][nt][r] = 0.f;
    float lacc = 0.f;
    const int Rp = wrp * 32;

    int m = 0;
    while (blk + (m >> 4) * NBLK < NCT) {
        __syncthreads();
        issueC(m + 3);
        cp_wait<2>();
        __syncthreads();

        const float* cur = ring + (m & 3) * (SLABC * PS);
        const int s = m & 15;
        {
            unsigned a[2][4];
#pragma unroll
            for (int mt = 0; mt < 2; mt++) {
                const float* base = cur + (2 * tg) * PS + Rp + 16 * mt + g;
                a[mt][0] = pack_h2(base[0],          base[PS]);
                a[mt][1] = pack_h2(base[8],          base[PS + 8]);
                a[mt][2] = pack_h2(base[8 * PS],     base[9 * PS]);
                a[mt][3] = pack_h2(base[8 * PS + 8], base[9 * PS + 8]);
            }
            const int cpi = s * 8;
#pragma unroll
            for (int nt = 0; nt < 3; nt++) {
                unsigned b[2];
                b[0] = sbh[(cpi + tg) * WS + 8 * nt + g];
                b[1] = sbh[(cpi + tg + 4) * WS + 8 * nt + g];
                mma_f16(acc[0][nt], a[0], b);
                mma_f16(acc[1][nt], a[1], b);
            }
        }

        if (s == 15) {
            const int tile = blk + (m >> 4) * NBLK;
            const int pb = tile * CTILE + Rp;
            float2 npr[4];
#pragma unroll
            for (int mt = 0; mt < 2; mt++)
#pragma unroll
                for (int rh = 0; rh < 2; rh++)
                    npr[2 * mt + rh] = g_npr[pb + 16 * mt + g + 8 * rh];

            float sume[4];
#pragma unroll
            for (int mt = 0; mt < 2; mt++)
#pragma unroll
                for (int rh = 0; rh < 2; rh++) {
                    const int i = 2 * mt + rh;
                    const float sc = npr[i].y * (1.0f / TAU);
                    float sum = 0.f;
#pragma unroll
                    for (int nt = 0; nt < 3; nt++)
#pragma unroll
                        for (int rl = 0; rl < 2; rl++) {
                            const int col = 8 * nt + 2 * tg + rl;
                            const float v = acc[mt][nt][2 * rh + rl];
                            sum += (col < K_) ? __expf(v * sc) : 0.f;
                        }
                    sume[i] = sum;
                }
#pragma unroll
            for (int i = 0; i < 4; i++) {
                sume[i] += __shfl_xor_sync(0xffffffffu, sume[i], 1);
                sume[i] += __shfl_xor_sync(0xffffffffu, sume[i], 2);
            }
            if (tg == 0) {
#pragma unroll
                for (int i = 0; i < 4; i++)
                    lacc += npr[i].x * __logf(sume[i]);   // |logit| <= ~14.3
            }
#pragma unroll
            for (int mt = 0; mt < 2; mt++)
#pragma unroll
                for (int nt = 0; nt < 3; nt++)
#pragma unroll
                    for (int r = 0; r < 4; r++) acc[mt][nt][r] = 0.f;
        }
        m++;
    }

    // block-reduce lacc -> g_lsepart[blk]
    __syncthreads();
    sred[tid] = lacc;
    __syncthreads();
    for (int st = 128; st > 0; st >>= 1) {
        if (tid < st) sred[tid] += sred[tid + st];
        __syncthreads();
    }
    if (tid == 0) g_lsepart[blk] = sred[0];

    // ================= PHASE D (last CTA) =================
    if (tid == 0) {
        __threadfence();
        sflag = (int)atomicAdd(&g_c2, 1u);
    }
    __syncthreads();
    if (sflag == NBLK - 1) {
        __threadfence();
        float a = 0.f;
        for (int i = tid; i < NBLK; i += 256) a += g_lsepart[i];
        float nk = 0.f;
        if (tid < K_) nk = g_normk[tid];
        int np = 0;
        for (int i = tid; i < NBLK; i += 256) np += g_nposblk[i];

        sred[tid]  = a - nk * (1.0f / TAU);
        sredi[tid] = np;
        __syncthreads();
        for (int s = 128; s > 0; s >>= 1) {
            if (tid < s) { sred[tid] += sred[tid + s]; sredi[tid] += sredi[tid + s]; }
            __syncthreads();
        }
        if (tid == 0) {
            out[0] = sred[0] / (float)sredi[0];
            g_c1 = 0;                 // safe: every CTA passed c1 before c2 arrive
            g_c2 = 0;
        }
    }
}

// ============================================================
// launch: ONE kernel
// ============================================================
extern "C" void kernel_launch(void* const* d_in, const int* in_sizes, int n_in,
                              void* d_out, int out_size)
{
    const float* feat = (const float*)d_in[0];
    const float* gt   = (const float*)d_in[1];
    float* out        = (float*)d_out;

    const int smemA = (2 * C_ * TSA + 2 * 16 * WS + 2 * K_ * TQ + 256) * 4; // 92928 B
    const int smemC = (4 * SLABC * PS) * 4 + (128 * WS) * 4;                // 87040 B
    const int smem  = smemA > smemC ? smemA : smemC;
    cudaFuncSetAttribute(kF, cudaFuncAttributeMaxDynamicSharedMemorySize, smem);

    kF<<<NBLK, 256, smem>>>(feat, gt, out);
}

// round 16
// speedup vs baseline: 1.1275x; 1.1275x over previous
#include <cuda_runtime.h>
#include <cuda_fp16.h>
#include <math.h>

#define TAU 0.07f
#define EPSN 1e-12f

constexpr int B_   = 4;
constexpr int C_   = 256;
constexpr int K_   = 19;
constexpr int HW   = 65536;          // 256*256
constexpr int P    = B_ * HW;        // 262144
constexpr int NBLK = 296;            // persistent CTAs (2/SM)
constexpr int KC   = K_ * C_;        // 4864
// kA
constexpr int TQ   = 32;             // pixels per tile
constexpr int NTA  = P / TQ;         // 8192 tiles
constexpr int TSA  = 40;             // tile pixel-stride (40%32==8 -> conflict-free)
constexpr int WS   = 40;             // class stride (half2 units)
// kC (warp-private streaming)
constexpr int WPC  = 8;              // warps per CTA
constexpr int GW   = NBLK * WPC;     // 2368 global warps
constexpr int TPX  = 16;             // pixels per warp-tile
constexpr int NWT  = P / TPX;        // 16384 warp-tiles
constexpr int PSW  = 20;             // padded pixel stride (8tg+g bijective)
constexpr int CCH  = 16;             // channels per chunk
constexpr int RING = 4;              // ring slots per warp
constexpr int WBUF = RING * CCH * PSW;   // floats per warp ring = 1280

// ---- scratch (static __device__, no allocation) ----
__device__ float    g_part[(size_t)NBLK * KC];
__device__ float2   g_npr[P];        // (npos, rn) per pixel
__device__ float    g_k0n[KC];
__device__ float    g_normk[K_];
__device__ int      g_nposblk[NBLK];
__device__ float    g_lsepart[NBLK];
__device__ unsigned g_c2;            // kD last-CTA counter

// ---- PTX helpers ----
__device__ __forceinline__ unsigned smem_u32(const void* p) {
    return (unsigned)__cvta_generic_to_shared(p);
}
__device__ __forceinline__ void cp16(unsigned dst, const void* src) {
    asm volatile("cp.async.cg.shared.global [%0], [%1], 16;\n" :: "r"(dst), "l"(src));
}
__device__ __forceinline__ void cp_commit() { asm volatile("cp.async.commit_group;\n" ::: "memory"); }
template<int N> __device__ __forceinline__ void cp_wait() {
    asm volatile("cp.async.wait_group %0;\n" :: "n"(N) : "memory");
}
__device__ __forceinline__ unsigned pack_h2(float lo, float hi) {
    unsigned r;
    asm("cvt.rn.f16x2.f32 %0, %1, %2;" : "=r"(r) : "f"(hi), "f"(lo));
    return r;
}
__device__ __forceinline__ void mma_f16(float* d, const unsigned* a, const unsigned* b) {
    asm volatile(
        "mma.sync.aligned.m16n8k16.row.col.f32.f16.f16.f32 "
        "{%0,%1,%2,%3}, {%4,%5,%6,%7}, {%8,%9}, {%0,%1,%2,%3};\n"
        : "+f"(d[0]), "+f"(d[1]), "+f"(d[2]), "+f"(d[3])
        : "r"(a[0]), "r"(a[1]), "r"(a[2]), "r"(a[3]), "r"(b[0]), "r"(b[1]));
}

// ============================================================
// Kernel A: k0[c,k] = sum_p feat[c,p]*w[p,k]
//   296 CTAs (2/SM), ring-2 of 32-pixel tiles  (unchanged R11)
// ============================================================
extern "C" __global__ void __launch_bounds__(256, 2)
kA(const float* __restrict__ feat, const float* __restrict__ gt)
{
    extern __shared__ float sm[];
    float*    fbuf = sm;                               // 2 x [256][40]
    unsigned* wk   = (unsigned*)(sm + 2 * C_ * TSA);   // 2 x [16 pairs][40]
    float*    sgt  = (float*)(wk + 2 * 16 * WS);       // 2 x [19][32]
    float*    ssq  = sgt + 2 * K_ * TQ;                // [256]

    const int tid  = threadIdx.x;
    const int blk  = blockIdx.x;
    const int lane = tid & 31;
    const int wrp  = tid >> 5;
    const int g    = lane >> 2;
    const int tg   = lane & 3;
    const int qi   = tid & 7;
    const int cr   = tid >> 3;

    for (int i = tid; i < 2 * 16 * WS; i += 256) wk[i] = 0u;
    __syncthreads();

    float acc[2][3][4];
#pragma unroll
    for (int mt = 0; mt < 2; mt++)
#pragma unroll
        for (int nt = 0; nt < 3; nt++)
#pragma unroll
            for (int r = 0; r < 4; r++) acc[mt][nt][r] = 0.f;
    int np_acc = 0;

    auto issue = [&](int jj) {
        const int t = blk + jj * NBLK;
        if (t < NTA) {
            float* buf = fbuf + (jj & 1) * (C_ * TSA);
            const int p0  = t * TQ;
            const int b   = p0 >> 16;
            const int hw0 = p0 & 65535;
            const float* fb = feat + (size_t)b * C_ * HW + hw0;
#pragma unroll
            for (int i = 0; i < 8; i++) {
                const int c = cr + 32 * i;
                cp16(smem_u32(buf + c * TSA + qi * 4), fb + (size_t)c * HW + qi * 4);
            }
            if (tid < (K_ * TQ) / 4) {
                const int k  = tid >> 3;
                const int qq = (tid & 7) * 4;
                cp16(smem_u32(sgt + (jj & 1) * (K_ * TQ) + k * TQ + qq),
                     gt + (size_t)b * K_ * HW + hw0 + (size_t)k * HW + qq);
            }
        }
        cp_commit();
    };

    auto dossq = [&](int jj) {
        const float* col = fbuf + (jj & 1) * (C_ * TSA) + (wrp * 32) * TSA + lane;
        float a0 = 0.f, a1 = 0.f, a2 = 0.f, a3 = 0.f;
#pragma unroll
        for (int cc = 0; cc < 32; cc += 4) {
            const float v0 = col[(cc + 0) * TSA];
            const float v1 = col[(cc + 1) * TSA];
            const float v2 = col[(cc + 2) * TSA];
            const float v3 = col[(cc + 3) * TSA];
            a0 = fmaf(v0, v0, a0); a1 = fmaf(v1, v1, a1);
            a2 = fmaf(v2, v2, a2); a3 = fmaf(v3, v3, a3);
        }
        ssq[wrp * 32 + lane] = (a0 + a1) + (a2 + a3);
    };

    auto domask = [&](int jj, int t) {
        if (tid < TQ) {
            const int q = tid;
            float s = 0.f;
#pragma unroll
            for (int w = 0; w < 8; w++) s += ssq[w * 32 + q];
            const float rn = 1.0f / fmaxf(sqrtf(s), EPSN);
            const __half rnh  = __float2half_rn(rn);
            const __half zero = __float2half_rn(0.f);
            __half* wh = (__half*)(wk + (jj & 1) * (16 * WS));
            const float* gtt = sgt + (jj & 1) * (K_ * TQ);
            const int base = ((q >> 1) * WS) * 2 + (q & 1);
            int np = 0;
#pragma unroll
            for (int k = 0; k < K_; k++) {
                const bool pos = (gtt[k * TQ + q] == 1.0f);
                wh[base + 2 * k] = pos ? rnh : zero;
                np += pos ? 1 : 0;
            }
            g_npr[t * TQ + q] = make_float2((float)np, rn);
            np_acc += np;
        }
    };

    auto compute = [&](int jj) {
        const float*    cur = fbuf + (jj & 1) * (C_ * TSA);
        const unsigned* wks = wk + (jj & 1) * (16 * WS);
        const int R = wrp * 32;
#pragma unroll
        for (int q16 = 0; q16 < 2; q16++) {
            const int p0 = 16 * q16;
            unsigned a[2][4];
#pragma unroll
            for (int mt = 0; mt < 2; mt++) {
                const float* base = cur + (R + 16 * mt + g) * TSA + p0 + 2 * tg;
                const float2 u0 = *(const float2*)(base);
                const float2 u1 = *(const float2*)(base + 8 * TSA);
                const float2 u2 = *(const float2*)(base + 8);
                const float2 u3 = *(const float2*)(base + 8 * TSA + 8);
                a[mt][0] = pack_h2(u0.x, u0.y);
                a[mt][1] = pack_h2(u1.x, u1.y);
                a[mt][2] = pack_h2(u2.x, u2.y);
                a[mt][3] = pack_h2(u3.x, u3.y);
            }
#pragma unroll
            for (int nt = 0; nt < 3; nt++) {
                unsigned b[2];
                b[0] = wks[(p0 / 2 + tg) * WS + 8 * nt + g];
                b[1] = wks[(p0 / 2 + tg + 4) * WS + 8 * nt + g];
                mma_f16(acc[0][nt], a[0], b);
                mma_f16(acc[1][nt], a[1], b);
            }
        }
    };

    issue(0); issue(1);
    int j = 0;
    while (blk + j * NBLK < NTA) {
        cp_wait<1>();
        __syncthreads();
        dossq(j);
        __syncthreads();
        domask(j, blk + j * NBLK);
        __syncthreads();
        compute(j);
        __syncthreads();
        issue(j + 2);
        j++;
    }

    const int R = wrp * 32;
#pragma unroll
    for (int mt = 0; mt < 2; mt++)
#pragma unroll
        for (int nt = 0; nt < 3; nt++)
#pragma unroll
            for (int r = 0; r < 4; r++) {
                const int row = R + 16 * mt + g + 8 * (r >> 1);
                const int col = 8 * nt + 2 * tg + (r & 1);
                if (col < K_)
                    g_part[(size_t)blk * KC + col * C_ + row] = acc[mt][nt][r];
            }

    __syncthreads();
    int* si = (int*)ssq;
    if (tid < TQ) si[tid] = np_acc;
    __syncthreads();
    if (tid == 0) {
        int s = 0;
        for (int i = 0; i < TQ; i++) s += si[i];
        g_nposblk[blk] = s;
    }
}

// ============================================================
// Kernel B: reduce k0 partials -> k0n, norms (1024 thr)
// ============================================================
extern "C" __global__ void kB()
{
    const int k = blockIdx.x;
    const int tid = threadIdx.x;
    const int c = tid & 255;
    const int s = tid >> 8;
    float v = 0.f;
    const int b0 = s * 74, b1 = b0 + 74;
#pragma unroll 4
    for (int b = b0; b < b1; b++)
        v += g_part[(size_t)b * KC + k * C_ + c];

    __shared__ float red[1024];
    red[tid] = v;
    __syncthreads();
    float w = 0.f;
    if (tid < 256) w = red[c] + red[c + 256] + red[c + 512] + red[c + 768];
    __syncthreads();
    if (tid < 256) red[c] = w * w;
    __syncthreads();
    for (int st = 128; st > 0; st >>= 1) {
        if (tid < st) red[tid] += red[tid + st];
        __syncthreads();
    }
    const float ssq = red[0];
    const float inv = 1.0f / fmaxf(sqrtf(ssq), EPSN);
    if (tid < 256) g_k0n[k * C_ + c] = w * inv;
    if (tid == 0)  g_normk[k] = ssq * inv;   // = k0n . k0
}

// ============================================================
// Kernel C: logits + lse — BARRIER-FREE warp-private streaming.
//   Each warp owns 16-pixel tiles; private ring-4 of 16ch x 16px
//   chunks; only __syncwarp in the mainloop. kD folded (last CTA).
// ============================================================
extern "C" __global__ void __launch_bounds__(256, 2)
kC(const float* __restrict__ feat, float* __restrict__ out)
{
    extern __shared__ float sm[];
    float*    wring = sm;                            // 8 warps x WBUF floats
    unsigned* sbh   = (unsigned*)(sm + WPC * WBUF);  // [128 ch-pairs][40] half2
    __shared__ float sred[256];
    __shared__ int   sredi[256];
    __shared__ int   sflag;

    const int tid  = threadIdx.x;
    const int blk  = blockIdx.x;
    const int lane = tid & 31;
    const int wrp  = tid >> 5;
    const int g    = lane >> 2;
    const int tg   = lane & 3;

    // prototypes -> half2 channel-pairs (one-time, one barrier)
    for (int i = tid; i < 128 * WS; i += 256) sbh[i] = 0u;
    __syncthreads();
    for (int idx = tid; idx < 128 * K_; idx += 256) {
        const int cp = idx / K_;
        const int k  = idx - cp * K_;
        sbh[cp * WS + k] = pack_h2(g_k0n[k * C_ + 2 * cp],
                                   g_k0n[k * C_ + 2 * cp + 1]);
    }
    __syncthreads();

    float* ring = wring + wrp * WBUF;      // warp-private ring
    const int gw = blk * WPC + wrp;        // global warp id

    auto issue = [&](int m) {
        const int tile = gw + (m >> 4) * GW;
        if (tile < NWT) {
            const int s  = m & 15;
            const int c0 = s * CCH;
            float* buf = ring + (m & 3) * (CCH * PSW);
            const int p0  = tile * TPX;
            const int b   = p0 >> 16;
            const int hw0 = p0 & 65535;
            const float* fb = feat + (size_t)b * C_ * HW + hw0;
#pragma unroll
            for (int i = 0; i < 2; i++) {           // 64 cp16 per chunk, 2/lane
                const int idx = lane + 32 * i;
                const int cl = idx >> 2;            // channel 0..15
                const int sl = idx & 3;             // 16B slot 0..3
                cp16(smem_u32(buf + cl * PSW + sl * 4),
                     fb + (size_t)(c0 + cl) * HW + sl * 4);
            }
        }
        cp_commit();
    };

    float acc[3][4];
#pragma unroll
    for (int nt = 0; nt < 3; nt++)
#pragma unroll
        for (int r = 0; r < 4; r++) acc[nt][r] = 0.f;
    float lacc = 0.f;

    issue(0); issue(1); issue(2);

    int m = 0;
    while (gw + (m >> 4) * GW < NWT) {
        issue(m + 3);
        cp_wait<3>();              // chunk m complete (per-thread groups)
        __syncwarp();

        const float* cur = ring + (m & 3) * (CCH * PSW);
        const int s = m & 15;
        {
            unsigned a[4];
            const float* base = cur + (2 * tg) * PSW + g;
            a[0] = pack_h2(base[0],           base[PSW]);
            a[1] = pack_h2(base[8],           base[PSW + 8]);
            a[2] = pack_h2(base[8 * PSW],     base[9 * PSW]);
            a[3] = pack_h2(base[8 * PSW + 8], base[9 * PSW + 8]);
            const int cpi = s * 8;
#pragma unroll
            for (int nt = 0; nt < 3; nt++) {
                unsigned b[2];
                b[0] = sbh[(cpi + tg) * WS + 8 * nt + g];
                b[1] = sbh[(cpi + tg + 4) * WS + 8 * nt + g];
                mma_f16(acc[nt], a, b);
            }
        }
        __syncwarp();              // all lanes done with slot m before reuse

        if (s == 15) {
            // ---- epilogue: 16 pixels, register-only ----
            const int tile = gw + (m >> 4) * GW;
            const int pb = tile * TPX;
            float2 npr[2];
            npr[0] = g_npr[pb + g];
            npr[1] = g_npr[pb + g + 8];

            float sume[2];
#pragma unroll
            for (int rh = 0; rh < 2; rh++) {
                const float sc = npr[rh].y * (1.0f / TAU);
                float sum = 0.f;
#pragma unroll
                for (int nt = 0; nt < 3; nt++)
#pragma unroll
                    for (int rl = 0; rl < 2; rl++) {
                        const int col = 8 * nt + 2 * tg + rl;
                        const float v = acc[nt][2 * rh + rl];
                        sum += (col < K_) ? __expf(v * sc) : 0.f;
                    }
                sume[rh] = sum;
            }
#pragma unroll
            for (int i = 0; i < 2; i++) {
                sume[i] += __shfl_xor_sync(0xffffffffu, sume[i], 1);
                sume[i] += __shfl_xor_sync(0xffffffffu, sume[i], 2);
            }
            if (tg == 0) {
#pragma unroll
                for (int i = 0; i < 2; i++)
                    lacc += npr[i].x * __logf(sume[i]);   // |logit| <= ~14.3
            }
#pragma unroll
            for (int nt = 0; nt < 3; nt++)
#pragma unroll
                for (int r = 0; r < 4; r++) acc[nt][r] = 0.f;
        }
        m++;
    }

    // block-reduce lacc
    __syncthreads();
    sred[tid] = lacc;
    __syncthreads();
    for (int st = 128; st > 0; st >>= 1) {
        if (tid < st) sred[tid] += sred[tid + st];
        __syncthreads();
    }
    if (tid == 0) g_lsepart[blk] = sred[0];

    // ---- folded kD: last CTA computes final scalar ----
    if (tid == 0) {
        __threadfence();
        sflag = (int)atomicAdd(&g_c2, 1u);
    }
    __syncthreads();
    if (sflag == NBLK - 1) {
        __threadfence();
        float a = 0.f;
        for (int i = tid; i < NBLK; i += 256) a += g_lsepart[i];
        float nk = 0.f;
        if (tid < K_) nk = g_normk[tid];
        int np = 0;
        for (int i = tid; i < NBLK; i += 256) np += g_nposblk[i];

        sred[tid]  = a - nk * (1.0f / TAU);
        sredi[tid] = np;
        __syncthreads();
        for (int s = 128; s > 0; s >>= 1) {
            if (tid < s) { sred[tid] += sred[tid + s]; sredi[tid] += sredi[tid + s]; }
            __syncthreads();
        }
        if (tid == 0) {
            out[0] = sred[0] / (float)sredi[0];
            g_c2 = 0;            // reset for graph replay (all CTAs already arrived)
        }
    }
}

// ============================================================
// launch: 3 kernels
// ============================================================
extern "C" void kernel_launch(void* const* d_in, const int* in_sizes, int n_in,
                              void* d_out, int out_size)
{
    const float* feat = (const float*)d_in[0];
    const float* gt   = (const float*)d_in[1];
    float* out        = (float*)d_out;

    const int smemA = (2 * C_ * TSA + 2 * 16 * WS + 2 * K_ * TQ + 256) * 4; // 92928 B
    const int smemC = (WPC * WBUF) * 4 + (128 * WS) * 4;                    // 61440 B
    cudaFuncSetAttribute(kA, cudaFuncAttributeMaxDynamicSharedMemorySize, smemA);
    cudaFuncSetAttribute(kC, cudaFuncAttributeMaxDynamicSharedMemorySize, smemC);

    kA<<<NBLK, 256, smemA>>>(feat, gt);
    kB<<<K_, 1024>>>();
    kC<<<NBLK, 256, smemC>>>(feat, out);
}